// round 8
// baseline (speedup 1.0000x reference)
#include <cuda_runtime.h>

#define B_   2
#define NT_  1024
#define ND_  512
#define NH_  196
#define KL_  128
#define ROWS2_ 4

__device__ float g_hm[B_ * NT_ * NH_];  // pooled hidden (after leaky+mean), pre-W1

typedef unsigned long long u64t;

__device__ __forceinline__ u64t pack2(float x, float y) {
    u64t r; asm("mov.b64 %0, {%1, %2};" : "=l"(r) : "f"(x), "f"(y)); return r;
}
__device__ __forceinline__ float2 unpack2(u64t v) {
    float2 r; asm("mov.b64 {%0, %1}, %2;" : "=f"(r.x), "=f"(r.y) : "l"(v)); return r;
}
__device__ __forceinline__ u64t ffma2(u64t a, u64t b, u64t c) {
    u64t d; asm("fma.rn.f32x2 %0, %1, %2, %3;" : "=l"(d) : "l"(a), "l"(b), "l"(c)); return d;
}
__device__ __forceinline__ u64t add2(u64t a, u64t b) {
    u64t d; asm("add.rn.f32x2 %0, %1, %2;" : "=l"(d) : "l"(a), "l"(b)); return d;
}

// ---------------------------------------------------------------------------
// Per-h weight fold (basis folded into W0 columns), done per thread in-kernel.
// s layout: 0:N 1:|x0| 2-7:x0b 8:|vb| 9-14:vbb 15:|x| 16-21:xb 22:|v| 23-28:vb
// ---------------------------------------------------------------------------
__device__ __forceinline__ void fold_wj(const float* __restrict__ W0,
                                        const float* __restrict__ bs,
                                        int h, float* wjv) {
    const float* W0h = W0 + h;
    wjv[0] = W0h[15 * NH_];                  // |x|
    wjv[4] = W0h[22 * NH_];                  // |vc|
#pragma unroll
    for (int d = 0; d < 3; d++) {
        float m1 = 0.f, m2 = 0.f;
#pragma unroll
        for (int k = 0; k < 6; k++) {
            float bb = bs[k * 3 + d];
            m1 += bb * W0h[(16 + k) * NH_];
            m2 += bb * W0h[(23 + k) * NH_];
        }
        wjv[1 + d] = m1;
        wjv[5 + d] = m2;
    }
}

__device__ __forceinline__ float fold_C(const float* __restrict__ W0,
                                        const float* __restrict__ b0,
                                        const float* __restrict__ bs,
                                        int h, float Nv, float x0n, float vbn,
                                        const float* uu, const float* qq) {
    const float* W0h = W0 + h;
    float C = b0[h] + Nv * W0h[0] + x0n * W0h[1 * NH_] + vbn * W0h[8 * NH_];
#pragma unroll
    for (int d = 0; d < 3; d++) {
        float m0x = 0.f, m0v = 0.f;
#pragma unroll
        for (int k = 0; k < 6; k++) {
            float bb = bs[k * 3 + d];
            m0x += bb * W0h[(2 + k) * NH_];
            m0v += bb * W0h[(9 + k) * NH_];
        }
        C += uu[d] * m0x + qq[d] * m0v;
    }
    return C;
}

// ---------------------------------------------------------------------------
// Main kernel (R1/R5-proven structure + fused fold): one CTA per (b,i),
// 128 threads, 2 h per thread (h0 = t, h1 = t + 128).
// ---------------------------------------------------------------------------
__global__ __launch_bounds__(128) void main_kernel(
    const float* __restrict__ x0g, const float* __restrict__ xg,
    const float* __restrict__ Ng,  const float* __restrict__ basisg,
    const float* __restrict__ vg,  const float* __restrict__ W0,
    const float* __restrict__ b0) {
    __shared__ float4 ftr4[8 * 128];           // features transposed: ftr[f][512]
    float* ftr = (float*)ftr4;
    __shared__ float red[32];

    int t = threadIdx.x;
    int blk = blockIdx.x;
    int b = blk >> 10, i = blk & (NT_ - 1);
    int lane = t & 31, w = t >> 5;
    int base = (b * NT_ + i) * ND_ * 3;
    const float* bs = basisg + b * 18;

    int h0 = t;
    int h1i = t + 128;
    int h1c = (h1i < NH_) ? h1i : (NH_ - 1);   // clamped for reads

    // --- phase 0: fold per-j weights for both h's (registers) ---
    float w0s[8], w1s[8];
    fold_wj(W0, bs, h0, w0s);
    fold_wj(W0, bs, h1c, w1s);

    // --- phase 1: vbulk (keep v in regs for phase 2) ---
    float vxr[4], vyr[4], vzr[4];
    float s0 = 0.f, s1 = 0.f, s2 = 0.f;
#pragma unroll
    for (int r = 0; r < 4; r++) {
        int j = t + r * 128;
        const float* vp = vg + base + j * 3;
        float a = vp[0], bb = vp[1], c = vp[2];
        vxr[r] = a; vyr[r] = bb; vzr[r] = c;
        s0 += a; s1 += bb; s2 += c;
    }
#pragma unroll
    for (int off = 16; off; off >>= 1) {
        s0 += __shfl_xor_sync(0xffffffffu, s0, off);
        s1 += __shfl_xor_sync(0xffffffffu, s1, off);
        s2 += __shfl_xor_sync(0xffffffffu, s2, off);
    }
    if (lane == 0) { red[w * 8 + 0] = s0; red[w * 8 + 1] = s1; red[w * 8 + 2] = s2; }
    __syncthreads();
    float vb0 = (red[0] + red[8]  + red[16] + red[24]) * (1.f / ND_);
    float vb1 = (red[1] + red[9]  + red[17] + red[25]) * (1.f / ND_);
    float vb2 = (red[2] + red[10] + red[18] + red[26]) * (1.f / ND_);
    __syncthreads();

    // --- phase 2: stage per-j features + per-feature sums ---
    float fs[8] = {0.f, 0.f, 0.f, 0.f, 0.f, 0.f, 0.f, 0.f};
#pragma unroll
    for (int r = 0; r < 4; r++) {
        int j = t + r * 128;
        const float* xp = xg + base + j * 3;
        float a = xp[0], bb = xp[1], c = xp[2];
        float d  = a * a + bb * bb + c * c;
        float ri = rsqrtf(d);
        float n  = d * ri;
        float e1 = a * ri, e2 = bb * ri, e3 = c * ri;
        ftr[0 * 512 + j] = n;  ftr[1 * 512 + j] = e1;
        ftr[2 * 512 + j] = e2; ftr[3 * 512 + j] = e3;
        fs[0] += n; fs[1] += e1; fs[2] += e2; fs[3] += e3;
        float c0 = vxr[r] - vb0, c1 = vyr[r] - vb1, c2 = vzr[r] - vb2;
        d  = c0 * c0 + c1 * c1 + c2 * c2;
        ri = rsqrtf(d);
        n  = d * ri;
        e1 = c0 * ri; e2 = c1 * ri; e3 = c2 * ri;
        ftr[4 * 512 + j] = n;  ftr[5 * 512 + j] = e1;
        ftr[6 * 512 + j] = e2; ftr[7 * 512 + j] = e3;
        fs[4] += n; fs[5] += e1; fs[6] += e2; fs[7] += e3;
    }
#pragma unroll
    for (int off = 16; off; off >>= 1)
#pragma unroll
        for (int f = 0; f < 8; f++) fs[f] += __shfl_xor_sync(0xffffffffu, fs[f], off);
    if (lane == 0) {
#pragma unroll
        for (int f = 0; f < 8; f++) red[w * 8 + f] = fs[f];
    }
    __syncthreads();
    float fm[8];
#pragma unroll
    for (int f = 0; f < 8; f++)
        fm[f] = (red[f] + red[8 + f] + red[16 + f] + red[24 + f]) * (1.f / ND_);

    // --- per-i scalars + per-h constants C0, C1 (folded in-kernel) ---
    float Nv = Ng[b * NT_ + i];
    const float* x0p = x0g + (b * NT_ + i) * 3;
    float p0 = x0p[0], p1 = x0p[1], p2 = x0p[2];
    float d0 = p0 * p0 + p1 * p1 + p2 * p2;
    float ri0 = rsqrtf(d0);
    float x0n = d0 * ri0;
    float uu[3] = {p0 * ri0, p1 * ri0, p2 * ri0};
    float dv = vb0 * vb0 + vb1 * vb1 + vb2 * vb2;
    float riv = rsqrtf(dv);
    float vbn = dv * riv;
    float qq[3] = {vb0 * riv, vb1 * riv, vb2 * riv};

    float C0 = fold_C(W0, b0, bs, h0,  Nv, x0n, vbn, uu, qq);
    float C1 = fold_C(W0, b0, bs, h1c, Nv, x0n, vbn, uu, qq);

    u64t w0p[8], w1p[8];
#pragma unroll
    for (int f = 0; f < 8; f++) {
        w0p[f] = pack2(w0s[f], w0s[f]);
        w1p[f] = pack2(w1s[f], w1s[f]);
    }
    u64t C0p = pack2(C0, C0), C1p = pack2(C1, C1);

    // --- phase 3: hot loop. acc = sum_j |pre_j| for 2 h's, f32x2 over j ---
    const u64t MASK = 0x7FFFFFFF7FFFFFFFULL;
    u64t acc0 = 0ull, acc1 = 0ull;
#pragma unroll 1
    for (int j4 = 0; j4 < 512; j4 += 4) {
        ulonglong2 qv[8];
#pragma unroll
        for (int f = 0; f < 8; f++)
            qv[f] = *(const ulonglong2*)(ftr + f * 512 + j4);
        u64t p;
        p = C0p;
#pragma unroll
        for (int f = 0; f < 8; f++) p = ffma2(qv[f].x, w0p[f], p);
        acc0 = add2(acc0, p & MASK);
        p = C0p;
#pragma unroll
        for (int f = 0; f < 8; f++) p = ffma2(qv[f].y, w0p[f], p);
        acc0 = add2(acc0, p & MASK);
        p = C1p;
#pragma unroll
        for (int f = 0; f < 8; f++) p = ffma2(qv[f].x, w1p[f], p);
        acc1 = add2(acc1, p & MASK);
        p = C1p;
#pragma unroll
        for (int f = 0; f < 8; f++) p = ffma2(qv[f].y, w1p[f], p);
        acc1 = add2(acc1, p & MASK);
    }

    // mean(leaky) = 0.505*mean(pre) + 0.495*mean|pre|; mean(pre) is analytic
    float S0 = C0, S1 = C1;
#pragma unroll
    for (int f = 0; f < 8; f++) { S0 += fm[f] * w0s[f]; S1 += fm[f] * w1s[f]; }
    float2 e0 = unpack2(acc0), e1 = unpack2(acc1);
    float hm0 = 0.505f * S0 + (0.495f / ND_) * (e0.x + e0.y);
    float hm1 = 0.505f * S1 + (0.495f / ND_) * (e1.x + e1.y);
    float* hmp = g_hm + (b * NT_ + i) * NH_;
    hmp[h0] = hm0;
    if (h1i < NH_) hmp[h1i] = hm1;
}

// ---------------------------------------------------------------------------
// Tail v4: 512 CTAs x 4 rows, 256 threads — 2x the warps/SM of v3 to hide
// L2 latency. Batched weight LDGs (MLP=16) kept from v3.
// ---------------------------------------------------------------------------
__global__ __launch_bounds__(256) void tail_kernel(
    const float* __restrict__ W1, const float* __restrict__ b1,
    const float* __restrict__ W2, const float* __restrict__ b2,
    float* __restrict__ out)
{
    __shared__ __align__(16) float hm_s[ROWS2_ * NH_];   // 3.1 KB
    __shared__ __align__(16) float h2_s[ROWS2_ * NH_];   // 3.1 KB

    int t = threadIdx.x;
    int row0 = blockIdx.x * ROWS2_;

    // stage hm rows (contiguous, float4-coalesced; 4*196*4B = 3136B, 16B-mult)
    {
        const float4* src = (const float4*)(g_hm + row0 * NH_);
        float4* dst = (float4*)hm_s;
        for (int idx = t; idx < (ROWS2_ * NH_) / 4; idx += 256)
            dst[idx] = src[idx];
    }
    __syncthreads();

    // ---- layer 1: thread t (<196) owns column h = t, 4-row ILP ----
    if (t < NH_) {
        float bv = b1[t];
        float a0 = bv, a1 = bv, a2 = bv, a3 = bv;
#pragma unroll 1
        for (int k = 0; k < 192; k += 16) {
            float wv[16];
#pragma unroll
            for (int u = 0; u < 16; u++) wv[u] = W1[(k + u) * NH_ + t];
#pragma unroll
            for (int c4 = 0; c4 < 4; c4++) {
                int kk = k + c4 * 4;
                float4 h0 = *(const float4*)(hm_s + 0 * NH_ + kk);
                float4 h1 = *(const float4*)(hm_s + 1 * NH_ + kk);
                float4 h2 = *(const float4*)(hm_s + 2 * NH_ + kk);
                float4 h3 = *(const float4*)(hm_s + 3 * NH_ + kk);
                float w0 = wv[c4 * 4 + 0], w1 = wv[c4 * 4 + 1];
                float w2 = wv[c4 * 4 + 2], w3 = wv[c4 * 4 + 3];
                a0 = fmaf(h0.x, w0, a0); a0 = fmaf(h0.y, w1, a0);
                a0 = fmaf(h0.z, w2, a0); a0 = fmaf(h0.w, w3, a0);
                a1 = fmaf(h1.x, w0, a1); a1 = fmaf(h1.y, w1, a1);
                a1 = fmaf(h1.z, w2, a1); a1 = fmaf(h1.w, w3, a1);
                a2 = fmaf(h2.x, w0, a2); a2 = fmaf(h2.y, w1, a2);
                a2 = fmaf(h2.z, w2, a2); a2 = fmaf(h2.w, w3, a2);
                a3 = fmaf(h3.x, w0, a3); a3 = fmaf(h3.y, w1, a3);
                a3 = fmaf(h3.z, w2, a3); a3 = fmaf(h3.w, w3, a3);
            }
        }
        // epilogue k = 192..195
        {
            const int k = 192;
            float w0 = W1[(k + 0) * NH_ + t];
            float w1 = W1[(k + 1) * NH_ + t];
            float w2 = W1[(k + 2) * NH_ + t];
            float w3 = W1[(k + 3) * NH_ + t];
            float4 h0 = *(const float4*)(hm_s + 0 * NH_ + k);
            float4 h1 = *(const float4*)(hm_s + 1 * NH_ + k);
            float4 h2 = *(const float4*)(hm_s + 2 * NH_ + k);
            float4 h3 = *(const float4*)(hm_s + 3 * NH_ + k);
            a0 = fmaf(h0.x, w0, a0); a0 = fmaf(h0.y, w1, a0);
            a0 = fmaf(h0.z, w2, a0); a0 = fmaf(h0.w, w3, a0);
            a1 = fmaf(h1.x, w0, a1); a1 = fmaf(h1.y, w1, a1);
            a1 = fmaf(h1.z, w2, a1); a1 = fmaf(h1.w, w3, a1);
            a2 = fmaf(h2.x, w0, a2); a2 = fmaf(h2.y, w1, a2);
            a2 = fmaf(h2.z, w2, a2); a2 = fmaf(h2.w, w3, a2);
            a3 = fmaf(h3.x, w0, a3); a3 = fmaf(h3.y, w1, a3);
            a3 = fmaf(h3.z, w2, a3); a3 = fmaf(h3.w, w3, a3);
        }
        h2_s[0 * NH_ + t] = fmaxf(a0, 0.01f * a0);
        h2_s[1 * NH_ + t] = fmaxf(a1, 0.01f * a1);
        h2_s[2 * NH_ + t] = fmaxf(a2, 0.01f * a2);
        h2_s[3 * NH_ + t] = fmaxf(a3, 0.01f * a3);
    }
    __syncthreads();

    // ---- layer 2: t = (rowgroup t>>7 of 2 rows, output o = t&127) ----
    {
        int o  = t & (KL_ - 1);
        int r0 = (t >> 7) * 2;
        float bv = b2[o];
        float a0 = bv, a1 = bv;
#pragma unroll 1
        for (int k = 0; k < 192; k += 16) {
            float wv[16];
#pragma unroll
            for (int u = 0; u < 16; u++) wv[u] = W2[(k + u) * KL_ + o];
#pragma unroll
            for (int c4 = 0; c4 < 4; c4++) {
                int kk = k + c4 * 4;
                float4 h0 = *(const float4*)(h2_s + (r0 + 0) * NH_ + kk);
                float4 h1 = *(const float4*)(h2_s + (r0 + 1) * NH_ + kk);
                float w0 = wv[c4 * 4 + 0], w1 = wv[c4 * 4 + 1];
                float w2 = wv[c4 * 4 + 2], w3 = wv[c4 * 4 + 3];
                a0 = fmaf(h0.x, w0, a0); a0 = fmaf(h0.y, w1, a0);
                a0 = fmaf(h0.z, w2, a0); a0 = fmaf(h0.w, w3, a0);
                a1 = fmaf(h1.x, w0, a1); a1 = fmaf(h1.y, w1, a1);
                a1 = fmaf(h1.z, w2, a1); a1 = fmaf(h1.w, w3, a1);
            }
        }
        // epilogue k = 192..195
        {
            const int k = 192;
            float w0 = W2[(k + 0) * KL_ + o];
            float w1 = W2[(k + 1) * KL_ + o];
            float w2 = W2[(k + 2) * KL_ + o];
            float w3 = W2[(k + 3) * KL_ + o];
            float4 h0 = *(const float4*)(h2_s + (r0 + 0) * NH_ + k);
            float4 h1 = *(const float4*)(h2_s + (r0 + 1) * NH_ + k);
            a0 = fmaf(h0.x, w0, a0); a0 = fmaf(h0.y, w1, a0);
            a0 = fmaf(h0.z, w2, a0); a0 = fmaf(h0.w, w3, a0);
            a1 = fmaf(h1.x, w0, a1); a1 = fmaf(h1.y, w1, a1);
            a1 = fmaf(h1.z, w2, a1); a1 = fmaf(h1.w, w3, a1);
        }
        out[(row0 + r0 + 0) * KL_ + o] = a0;
        out[(row0 + r0 + 1) * KL_ + o] = a1;
    }
}

// ---------------------------------------------------------------------------
extern "C" void kernel_launch(void* const* d_in, const int* in_sizes, int n_in,
                              void* d_out, int out_size) {
    const float* x0    = (const float*)d_in[0];
    const float* x     = (const float*)d_in[1];
    const float* N     = (const float*)d_in[2];
    const float* basis = (const float*)d_in[3];
    const float* v     = (const float*)d_in[4];
    const float* W0    = (const float*)d_in[5];
    const float* b0    = (const float*)d_in[6];
    const float* W1    = (const float*)d_in[7];
    const float* b1    = (const float*)d_in[8];
    const float* W2    = (const float*)d_in[9];
    const float* b2    = (const float*)d_in[10];

    main_kernel<<<B_ * NT_, 128>>>(x0, x, N, basis, v, W0, b0);
    tail_kernel<<<(B_ * NT_) / ROWS2_, 256>>>(W1, b1, W2, b2, (float*)d_out);
}

// round 9
// speedup vs baseline: 1.6426x; 1.6426x over previous
#include <cuda_runtime.h>

#define B_   2
#define NT_  1024
#define ND_  512
#define NH_  196
#define HP_  256      // padded hidden dim (zeros for h >= 196)
#define KL_  128
#define ROWS2_ 4
#define KP_  208      // padded k stride for tail smem (13 blocks of 16)

// scratch (device globals: allocation-free)
__device__ float g_wj[B_ * 8 * HP_];    // per-j weights: [w_xn, M1x(3), w_vn, M1v(3)]
__device__ float g_wc[B_ * 10 * HP_];   // per-i weights: [w_N, w_x0n, M0x(3), w_vbn, M0v(3), b0]
__device__ float g_hm[B_ * NT_ * NH_];  // pooled hidden (after leaky+mean), pre-W1

typedef unsigned long long u64t;

__device__ __forceinline__ u64t pack2(float x, float y) {
    u64t r; asm("mov.b64 %0, {%1, %2};" : "=l"(r) : "f"(x), "f"(y)); return r;
}
__device__ __forceinline__ float2 unpack2(u64t v) {
    float2 r; asm("mov.b64 {%0, %1}, %2;" : "=f"(r.x), "=f"(r.y) : "l"(v)); return r;
}
__device__ __forceinline__ u64t ffma2(u64t a, u64t b, u64t c) {
    u64t d; asm("fma.rn.f32x2 %0, %1, %2, %3;" : "=l"(d) : "l"(a), "l"(b), "l"(c)); return d;
}
__device__ __forceinline__ u64t add2(u64t a, u64t b) {
    u64t d; asm("add.rn.f32x2 %0, %1, %2;" : "=l"(d) : "l"(a), "l"(b)); return d;
}

// ---------------------------------------------------------------------------
// Kernel 1: fold basis into W0 rows (tiny)
// ---------------------------------------------------------------------------
__global__ void precomp_kernel(const float* __restrict__ W0,
                               const float* __restrict__ b0,
                               const float* __restrict__ basis) {
    int b = blockIdx.x, h = threadIdx.x;
    float* wj = g_wj + b * 8 * HP_;
    float* wc = g_wc + b * 10 * HP_;
    if (h >= NH_) {
        for (int r = 0; r < 8;  r++) wj[r * HP_ + h] = 0.f;
        for (int r = 0; r < 10; r++) wc[r * HP_ + h] = 0.f;
        return;
    }
    const float* bs = basis + b * 6 * 3;
    wj[0 * HP_ + h] = W0[15 * NH_ + h];   // |x|
    wj[4 * HP_ + h] = W0[22 * NH_ + h];   // |vc|
    wc[0 * HP_ + h] = W0[0 * NH_ + h];    // N
    wc[1 * HP_ + h] = W0[1 * NH_ + h];    // |x0|
    wc[5 * HP_ + h] = W0[8 * NH_ + h];    // |vbulk|
    wc[9 * HP_ + h] = b0[h];
    for (int d = 0; d < 3; d++) {
        float m0x = 0.f, m0v = 0.f, m1 = 0.f, m2 = 0.f;
        for (int k = 0; k < 6; k++) {
            float bb = bs[k * 3 + d];
            m0x += bb * W0[(2  + k) * NH_ + h];
            m0v += bb * W0[(9  + k) * NH_ + h];
            m1  += bb * W0[(16 + k) * NH_ + h];
            m2  += bb * W0[(23 + k) * NH_ + h];
        }
        wj[(1 + d) * HP_ + h] = m1;
        wj[(5 + d) * HP_ + h] = m2;
        wc[(2 + d) * HP_ + h] = m0x;
        wc[(6 + d) * HP_ + h] = m0v;
    }
}

// ---------------------------------------------------------------------------
// Kernel 2 (R1/R5/R7-proven, untouched): one CTA per (b,i), 128 threads.
// ---------------------------------------------------------------------------
__global__ __launch_bounds__(128) void main_kernel(
    const float* __restrict__ x0g, const float* __restrict__ xg,
    const float* __restrict__ Ng,  const float* __restrict__ vg) {
    __shared__ float4 ftr4[8 * 128];           // features transposed: ftr[f][512]
    float* ftr = (float*)ftr4;
    __shared__ float red[32];

    int t = threadIdx.x;
    int blk = blockIdx.x;
    int b = blk >> 10, i = blk & (NT_ - 1);
    int lane = t & 31, w = t >> 5;
    int base = (b * NT_ + i) * ND_ * 3;

    // --- phase 1: vbulk (keep v in regs for phase 2) ---
    float vxr[4], vyr[4], vzr[4];
    float s0 = 0.f, s1 = 0.f, s2 = 0.f;
#pragma unroll
    for (int r = 0; r < 4; r++) {
        int j = t + r * 128;
        const float* vp = vg + base + j * 3;
        float a = vp[0], bb = vp[1], c = vp[2];
        vxr[r] = a; vyr[r] = bb; vzr[r] = c;
        s0 += a; s1 += bb; s2 += c;
    }
#pragma unroll
    for (int off = 16; off; off >>= 1) {
        s0 += __shfl_xor_sync(0xffffffffu, s0, off);
        s1 += __shfl_xor_sync(0xffffffffu, s1, off);
        s2 += __shfl_xor_sync(0xffffffffu, s2, off);
    }
    if (lane == 0) { red[w * 8 + 0] = s0; red[w * 8 + 1] = s1; red[w * 8 + 2] = s2; }
    __syncthreads();
    float vb0 = (red[0] + red[8]  + red[16] + red[24]) * (1.f / ND_);
    float vb1 = (red[1] + red[9]  + red[17] + red[25]) * (1.f / ND_);
    float vb2 = (red[2] + red[10] + red[18] + red[26]) * (1.f / ND_);
    __syncthreads();

    // --- phase 2: stage per-j features + per-feature sums ---
    float fs[8] = {0.f, 0.f, 0.f, 0.f, 0.f, 0.f, 0.f, 0.f};
#pragma unroll
    for (int r = 0; r < 4; r++) {
        int j = t + r * 128;
        const float* xp = xg + base + j * 3;
        float a = xp[0], bb = xp[1], c = xp[2];
        float d  = a * a + bb * bb + c * c;
        float ri = rsqrtf(d);
        float n  = d * ri;
        float e1 = a * ri, e2 = bb * ri, e3 = c * ri;
        ftr[0 * 512 + j] = n;  ftr[1 * 512 + j] = e1;
        ftr[2 * 512 + j] = e2; ftr[3 * 512 + j] = e3;
        fs[0] += n; fs[1] += e1; fs[2] += e2; fs[3] += e3;
        float c0 = vxr[r] - vb0, c1 = vyr[r] - vb1, c2 = vzr[r] - vb2;
        d  = c0 * c0 + c1 * c1 + c2 * c2;
        ri = rsqrtf(d);
        n  = d * ri;
        e1 = c0 * ri; e2 = c1 * ri; e3 = c2 * ri;
        ftr[4 * 512 + j] = n;  ftr[5 * 512 + j] = e1;
        ftr[6 * 512 + j] = e2; ftr[7 * 512 + j] = e3;
        fs[4] += n; fs[5] += e1; fs[6] += e2; fs[7] += e3;
    }
#pragma unroll
    for (int off = 16; off; off >>= 1)
#pragma unroll
        for (int f = 0; f < 8; f++) fs[f] += __shfl_xor_sync(0xffffffffu, fs[f], off);
    if (lane == 0) {
#pragma unroll
        for (int f = 0; f < 8; f++) red[w * 8 + f] = fs[f];
    }
    __syncthreads();
    float fm[8];
#pragma unroll
    for (int f = 0; f < 8; f++)
        fm[f] = (red[f] + red[8 + f] + red[16 + f] + red[24 + f]) * (1.f / ND_);

    // --- per-i constant C (cheap, redundant per thread) ---
    float Nv = Ng[b * NT_ + i];
    const float* x0p = x0g + (b * NT_ + i) * 3;
    float p0 = x0p[0], p1 = x0p[1], p2 = x0p[2];
    float d0 = p0 * p0 + p1 * p1 + p2 * p2;
    float ri0 = rsqrtf(d0);
    float x0n = d0 * ri0;
    float u0 = p0 * ri0, u1 = p1 * ri0, u2 = p2 * ri0;
    float dv = vb0 * vb0 + vb1 * vb1 + vb2 * vb2;
    float riv = rsqrtf(dv);
    float vbn = dv * riv;
    float q0 = vb0 * riv, q1 = vb1 * riv, q2 = vb2 * riv;

    const float* wj = g_wj + b * 8 * HP_;
    const float* wc = g_wc + b * 10 * HP_;
    int h0 = t, h1i = t + 128;

    float C0, C1;
    {
        float c;
        c  = wc[9 * HP_ + h0];
        c += Nv  * wc[0 * HP_ + h0];
        c += x0n * wc[1 * HP_ + h0];
        c += u0 * wc[2 * HP_ + h0] + u1 * wc[3 * HP_ + h0] + u2 * wc[4 * HP_ + h0];
        c += vbn * wc[5 * HP_ + h0];
        c += q0 * wc[6 * HP_ + h0] + q1 * wc[7 * HP_ + h0] + q2 * wc[8 * HP_ + h0];
        C0 = c;
        c  = wc[9 * HP_ + h1i];
        c += Nv  * wc[0 * HP_ + h1i];
        c += x0n * wc[1 * HP_ + h1i];
        c += u0 * wc[2 * HP_ + h1i] + u1 * wc[3 * HP_ + h1i] + u2 * wc[4 * HP_ + h1i];
        c += vbn * wc[5 * HP_ + h1i];
        c += q0 * wc[6 * HP_ + h1i] + q1 * wc[7 * HP_ + h1i] + q2 * wc[8 * HP_ + h1i];
        C1 = c;
    }

    float w0s[8], w1s[8];
    u64t  w0p[8], w1p[8];
#pragma unroll
    for (int f = 0; f < 8; f++) {
        w0s[f] = wj[f * HP_ + h0];
        w1s[f] = wj[f * HP_ + h1i];
        w0p[f] = pack2(w0s[f], w0s[f]);
        w1p[f] = pack2(w1s[f], w1s[f]);
    }
    u64t C0p = pack2(C0, C0), C1p = pack2(C1, C1);

    // --- phase 3: hot loop. acc = sum_j |pre_j| for 2 h's, f32x2 over j ---
    const u64t MASK = 0x7FFFFFFF7FFFFFFFULL;
    u64t acc0 = 0ull, acc1 = 0ull;
#pragma unroll 1
    for (int j4 = 0; j4 < 512; j4 += 4) {
        ulonglong2 qq[8];
#pragma unroll
        for (int f = 0; f < 8; f++)
            qq[f] = *(const ulonglong2*)(ftr + f * 512 + j4);
        u64t p;
        p = C0p;
#pragma unroll
        for (int f = 0; f < 8; f++) p = ffma2(qq[f].x, w0p[f], p);
        acc0 = add2(acc0, p & MASK);
        p = C0p;
#pragma unroll
        for (int f = 0; f < 8; f++) p = ffma2(qq[f].y, w0p[f], p);
        acc0 = add2(acc0, p & MASK);
        p = C1p;
#pragma unroll
        for (int f = 0; f < 8; f++) p = ffma2(qq[f].x, w1p[f], p);
        acc1 = add2(acc1, p & MASK);
        p = C1p;
#pragma unroll
        for (int f = 0; f < 8; f++) p = ffma2(qq[f].y, w1p[f], p);
        acc1 = add2(acc1, p & MASK);
    }

    // mean(leaky) = 0.505*mean(pre) + 0.495*mean|pre|; mean(pre) is analytic
    float S0 = C0, S1 = C1;
#pragma unroll
    for (int f = 0; f < 8; f++) { S0 += fm[f] * w0s[f]; S1 += fm[f] * w1s[f]; }
    float2 e0 = unpack2(acc0), e1 = unpack2(acc1);
    float hm0 = 0.505f * S0 + (0.495f / ND_) * (e0.x + e0.y);
    float hm1 = 0.505f * S1 + (0.495f / ND_) * (e1.x + e1.y);
    float* hmp = g_hm + (b * NT_ + i) * NH_;
    hmp[h0] = hm0;
    if (h1i < NH_) hmp[h1i] = hm1;
}

// ---------------------------------------------------------------------------
// Tail v5: 512 CTAs x 4 rows, 256 threads, software-pipelined weight prefetch.
// k padded to 13 blocks of 16 (KP_=208); weights beyond k=195 are zero, smem
// k-pads are zero, so the loop is uniform with no epilogue.
// ---------------------------------------------------------------------------
__global__ __launch_bounds__(256) void tail_kernel(
    const float* __restrict__ W1, const float* __restrict__ b1,
    const float* __restrict__ W2, const float* __restrict__ b2,
    float* __restrict__ out)
{
    __shared__ __align__(16) float hm_s[ROWS2_ * KP_];   // 3.3 KB (padded rows)
    __shared__ __align__(16) float h2_s[ROWS2_ * KP_];   // 3.3 KB

    int t = threadIdx.x;
    int row0 = blockIdx.x * ROWS2_;

    // zero both buffers (covers k-pads), then stage hm rows coalesced
    {
        float4* z0 = (float4*)hm_s;
        float4* z1 = (float4*)h2_s;
        for (int idx = t; idx < (ROWS2_ * KP_) / 4; idx += 256) {
            z0[idx] = make_float4(0.f, 0.f, 0.f, 0.f);
            z1[idx] = make_float4(0.f, 0.f, 0.f, 0.f);
        }
    }
    __syncthreads();
    {
        // 196 floats = 49 float4 per row; row base (row0+r)*196*4B is 16B-mult.
        const float4* src = (const float4*)g_hm;
        float4* dst = (float4*)hm_s;
        for (int idx = t; idx < ROWS2_ * 49; idx += 256) {
            int r = idx / 49, c = idx - r * 49;
            dst[r * (KP_ / 4) + c] = src[(row0 + r) * 49 + c];
        }
    }
    __syncthreads();

    // ---- layer 1: thread t (<196) owns column h = t, 4-row ILP, prefetch ----
    if (t < NH_) {
        float bv = b1[t];
        float a0 = bv, a1 = bv, a2 = bv, a3 = bv;
        float wc[16];
#pragma unroll
        for (int u = 0; u < 16; u++) wc[u] = W1[u * NH_ + t];
#pragma unroll 1
        for (int blk = 0; blk < 13; blk++) {
            int k  = blk * 16;
            int kn = k + 16;
            float wn[16];
#pragma unroll
            for (int u = 0; u < 16; u++)
                wn[u] = (kn + u < NH_) ? W1[(kn + u) * NH_ + t] : 0.f;
#pragma unroll
            for (int c4 = 0; c4 < 4; c4++) {
                int kk = k + c4 * 4;
                float4 h0 = *(const float4*)(hm_s + 0 * KP_ + kk);
                float4 h1 = *(const float4*)(hm_s + 1 * KP_ + kk);
                float4 h2 = *(const float4*)(hm_s + 2 * KP_ + kk);
                float4 h3 = *(const float4*)(hm_s + 3 * KP_ + kk);
                float w0 = wc[c4 * 4 + 0], w1 = wc[c4 * 4 + 1];
                float w2 = wc[c4 * 4 + 2], w3 = wc[c4 * 4 + 3];
                a0 = fmaf(h0.x, w0, a0); a0 = fmaf(h0.y, w1, a0);
                a0 = fmaf(h0.z, w2, a0); a0 = fmaf(h0.w, w3, a0);
                a1 = fmaf(h1.x, w0, a1); a1 = fmaf(h1.y, w1, a1);
                a1 = fmaf(h1.z, w2, a1); a1 = fmaf(h1.w, w3, a1);
                a2 = fmaf(h2.x, w0, a2); a2 = fmaf(h2.y, w1, a2);
                a2 = fmaf(h2.z, w2, a2); a2 = fmaf(h2.w, w3, a2);
                a3 = fmaf(h3.x, w0, a3); a3 = fmaf(h3.y, w1, a3);
                a3 = fmaf(h3.z, w2, a3); a3 = fmaf(h3.w, w3, a3);
            }
#pragma unroll
            for (int u = 0; u < 16; u++) wc[u] = wn[u];
        }
        h2_s[0 * KP_ + t] = fmaxf(a0, 0.01f * a0);
        h2_s[1 * KP_ + t] = fmaxf(a1, 0.01f * a1);
        h2_s[2 * KP_ + t] = fmaxf(a2, 0.01f * a2);
        h2_s[3 * KP_ + t] = fmaxf(a3, 0.01f * a3);
    }
    __syncthreads();

    // ---- layer 2: t = (rowgroup t>>7 of 2 rows, output o = t&127), prefetch ----
    {
        int o  = t & (KL_ - 1);
        int r0 = (t >> 7) * 2;
        float bv = b2[o];
        float a0 = bv, a1 = bv;
        float wc[16];
#pragma unroll
        for (int u = 0; u < 16; u++) wc[u] = W2[u * KL_ + o];
#pragma unroll 1
        for (int blk = 0; blk < 13; blk++) {
            int k  = blk * 16;
            int kn = k + 16;
            float wn[16];
#pragma unroll
            for (int u = 0; u < 16; u++)
                wn[u] = (kn + u < NH_) ? W2[(kn + u) * KL_ + o] : 0.f;
#pragma unroll
            for (int c4 = 0; c4 < 4; c4++) {
                int kk = k + c4 * 4;
                float4 h0 = *(const float4*)(h2_s + (r0 + 0) * KP_ + kk);
                float4 h1 = *(const float4*)(h2_s + (r0 + 1) * KP_ + kk);
                float w0 = wc[c4 * 4 + 0], w1 = wc[c4 * 4 + 1];
                float w2 = wc[c4 * 4 + 2], w3 = wc[c4 * 4 + 3];
                a0 = fmaf(h0.x, w0, a0); a0 = fmaf(h0.y, w1, a0);
                a0 = fmaf(h0.z, w2, a0); a0 = fmaf(h0.w, w3, a0);
                a1 = fmaf(h1.x, w0, a1); a1 = fmaf(h1.y, w1, a1);
                a1 = fmaf(h1.z, w2, a1); a1 = fmaf(h1.w, w3, a1);
            }
#pragma unroll
            for (int u = 0; u < 16; u++) wc[u] = wn[u];
        }
        out[(row0 + r0 + 0) * KL_ + o] = a0;
        out[(row0 + r0 + 1) * KL_ + o] = a1;
    }
}

// ---------------------------------------------------------------------------
extern "C" void kernel_launch(void* const* d_in, const int* in_sizes, int n_in,
                              void* d_out, int out_size) {
    const float* x0    = (const float*)d_in[0];
    const float* x     = (const float*)d_in[1];
    const float* N     = (const float*)d_in[2];
    const float* basis = (const float*)d_in[3];
    const float* v     = (const float*)d_in[4];
    const float* W0    = (const float*)d_in[5];
    const float* b0    = (const float*)d_in[6];
    const float* W1    = (const float*)d_in[7];
    const float* b1    = (const float*)d_in[8];
    const float* W2    = (const float*)d_in[9];
    const float* b2    = (const float*)d_in[10];

    precomp_kernel<<<B_, HP_>>>(W0, b0, basis);
    main_kernel<<<B_ * NT_, 128>>>(x0, x, N, v);
    tail_kernel<<<(B_ * NT_) / ROWS2_, 256>>>(W1, b1, W2, b2, (float*)d_out);
}